// round 6
// baseline (speedup 1.0000x reference)
#include <cuda_runtime.h>
#include <math.h>

// ---------------- Problem constants ----------------
#define S_LEN 2048
#define BATCH 64
#define FEAT  40
#define EMBD  128
#define HID   256

// Partition: 4 batch-groups x 32 hidden-slices = 128 persistent blocks
#define NBG  4
#define NSL  32
#define NBLK 128
#define TPB  256

// Padded K strides (floats). 44 % 32 == 268 % 32 == 12 -> u*stride covers all 8
// bank groups => conflict-free weight LDS; 4 consecutive batch rows also distinct.
#define XS   44      // x row stride, 176B (16B multiple)
#define HS   268     // h row stride, 1072B (16B multiple)

// SMEM layout (float offsets)
#define OFF_W0X  0                         // [32][44]  layer0 x-weights (folded)
#define OFF_W0H  (OFF_W0X + 32*XS)         // [32][268] layer0 h-weights (W_hh0)
#define OFF_W1A  (OFF_W0H + 32*HS)         // [32][268] layer1 h0-weights (W_ih1)
#define OFF_W1B  (OFF_W1A + 32*HS)         // [32][268] layer1 h1-weights (W_hh1)
#define OFF_XB   (OFF_W1B + 32*HS)         // [16][44]  x[s]
#define OFF_H0B  (OFF_XB + 16*XS)          // [16][268] h0[s-1]   (contiguous with H1B)
#define OFF_H1B  (OFF_H0B + 16*HS)         // [16][268] h1[s-2]
#define OFF_MBAR (OFF_H1B + 16*HS)
#define SMEM_FLOATS (OFF_MBAR + 4)
#define SMEM_BYTES  (SMEM_FLOATS * 4)      // ~145.7 KB

#define H_COPY_BYTES (2u * 16u * HS * 4u)  // 34304
#define X_COPY_BYTES (16u * XS * 4u)       // 2816
#define TX_BYTES     (H_COPY_BYTES + X_COPY_BYTES)

// ---------------- Device scratch (static, no runtime alloc) ----------------
__device__ float    g_Wfold[1024 * FEAT];
__device__ float    g_bias0[1024];
__device__ float    g_bias1[1024];
// h exchange: [parity][group][h0|h1][batch][HS] -- padded rows, contiguous per group
__device__ __align__(16) float g_hbuf[2][NBG][2][16][HS];
// pre-transposed x: [step][group][batch][XS] (one extra step of slack)
__device__ __align__(16) float g_xT[S_LEN + 1][NBG][16][XS];
__device__ unsigned g_flags[NBG * NSL];    // monotonic per-producer step flags
__device__ float    g_pdot[(size_t)S_LEN * BATCH * NSL];

// ---------------- Fast activations ----------------
__device__ __forceinline__ float sig_(float x)  { return 1.f / (1.f + __expf(-x)); }
__device__ __forceinline__ float tanh_(float x) { return __fdividef(2.f, 1.f + __expf(-2.f * x)) - 1.f; }

// ---------------- Packed f32x2 helpers ----------------
__device__ __forceinline__ void fma2(unsigned long long& acc,
                                     unsigned long long a, unsigned long long b)
{
    asm("fma.rn.f32x2 %0, %1, %2, %0;" : "+l"(acc) : "l"(a), "l"(b));
}
__device__ __forceinline__ unsigned long long pack2(float lo, float hi)
{
    unsigned long long r;
    asm("mov.b64 %0, {%1, %2};" : "=l"(r) : "f"(lo), "f"(hi));
    return r;
}
__device__ __forceinline__ float hsum2(unsigned long long p)
{
    float lo, hi;
    asm("mov.b64 {%0, %1}, %2;" : "=f"(lo), "=f"(hi) : "l"(p));
    return lo + hi;
}

// ---------------- Prologue kernels ----------------
__global__ void fold_kernel(const float* __restrict__ W_ih0,
                            const float* __restrict__ W_in,
                            const float* __restrict__ b_in,
                            const float* __restrict__ b_ih0,
                            const float* __restrict__ b_hh0,
                            const float* __restrict__ b_ih1,
                            const float* __restrict__ b_hh1)
{
    int r = blockIdx.x;          // 0..1023 gate row
    int t = threadIdx.x;         // 0..63
    if (t < FEAT) {
        float s = 0.f;
        for (int e = 0; e < EMBD; e++)
            s += W_ih0[r * EMBD + e] * W_in[e * FEAT + t];
        g_Wfold[r * FEAT + t] = s;
    } else if (t == 63) {
        float s = b_ih0[r] + b_hh0[r];
        for (int e = 0; e < EMBD; e++)
            s += W_ih0[r * EMBD + e] * b_in[e];
        g_bias0[r] = s;
        g_bias1[r] = b_ih1[r] + b_hh1[r];
    }
}

__global__ void init_kernel()
{
    float* hb = (float*)g_hbuf;
    const int total = 2 * NBG * 2 * 16 * HS;   // 274432
    for (int i = blockIdx.x * blockDim.x + threadIdx.x; i < total;
         i += gridDim.x * blockDim.x)
        hb[i] = 0.f;
    int i = blockIdx.x * blockDim.x + threadIdx.x;
    if (i < NBG * NSL) g_flags[i] = 0u;
}

// transpose x into [s][bg][b][XS] so the per-step x tile is one contiguous copy
__global__ void xT_kernel(const float* __restrict__ in_states)
{
    int idx = blockIdx.x * blockDim.x + threadIdx.x;   // (b*2048+s)*40+f order
    if (idx >= BATCH * S_LEN * FEAT) return;
    int f = idx % FEAT;
    int t = idx / FEAT;
    int s = t & (S_LEN - 1);
    int b = t >> 11;
    g_xT[s][b >> 4][b & 15][f] = in_states[idx];
}

// ---------------- Packed GEMM fragment: 4 gate-dots for one (u,b) cell ----------------
template<int NIT, int RS>
__device__ __forceinline__ void gpart2(const float* wrow, const float* inrow,
                                       unsigned long long& p0, unsigned long long& p1,
                                       unsigned long long& p2, unsigned long long& p3)
{
    const ulonglong2* hp = (const ulonglong2*)inrow;
    const ulonglong2* w0 = (const ulonglong2*)(wrow);
    const ulonglong2* w1 = (const ulonglong2*)(wrow + 8 * RS);
    const ulonglong2* w2 = (const ulonglong2*)(wrow + 16 * RS);
    const ulonglong2* w3 = (const ulonglong2*)(wrow + 24 * RS);
    #pragma unroll 8
    for (int k = 0; k < NIT; k++) {
        ulonglong2 h = hp[k];
        ulonglong2 a0 = w0[k];
        fma2(p0, a0.x, h.x); fma2(p0, a0.y, h.y);
        ulonglong2 a1 = w1[k];
        fma2(p1, a1.x, h.x); fma2(p1, a1.y, h.y);
        ulonglong2 a2 = w2[k];
        fma2(p2, a2.x, h.x); fma2(p2, a2.y, h.y);
        ulonglong2 a3 = w3[k];
        fma2(p3, a3.x, h.x); fma2(p3, a3.y, h.y);
    }
}

// ---------------- TMA 1D bulk copy ----------------
__device__ __forceinline__ void bulk_g2s(unsigned dst_smem, const void* src,
                                         unsigned bytes, unsigned mbar)
{
    asm volatile(
        "cp.async.bulk.shared::cluster.global.mbarrier::complete_tx::bytes "
        "[%0], [%1], %2, [%3];"
        :: "r"(dst_smem), "l"(src), "r"(bytes), "r"(mbar) : "memory");
}

__device__ __forceinline__ void mbar_wait(unsigned mbar, unsigned phase)
{
    unsigned done;
    asm volatile(
        "{\n\t.reg .pred p;\n\t"
        "mbarrier.try_wait.parity.acquire.cta.shared::cta.b64 p, [%1], %2;\n\t"
        "selp.b32 %0, 1, 0, p;\n\t}"
        : "=r"(done) : "r"(mbar), "r"(phase) : "memory");
    if (!done) {
        asm volatile(
            "{\n\t.reg .pred P1;\n\t"
            "WL_%=:\n\t"
            "mbarrier.try_wait.parity.acquire.cta.shared::cta.b64 P1, [%0], %1, 0x989680;\n\t"
            "@P1 bra.uni WD_%=;\n\t"
            "bra.uni WL_%=;\n\t"
            "WD_%=:\n\t}"
            :: "r"(mbar), "r"(phase) : "memory");
    }
}

// ---------------- Persistent wavefront recurrence kernel ----------------
__global__ void __launch_bounds__(TPB, 1)
lstm_persist(const float* __restrict__ W_hh0,
             const float* __restrict__ W_ih1,
             const float* __restrict__ W_hh1,
             const float* __restrict__ W_out)
{
    extern __shared__ float sm[];
    const int tid   = threadIdx.x;
    const int lane  = tid & 31;
    const int wid   = tid >> 5;
    const int slice = blockIdx.x & 31;   // hidden units slice*8 .. slice*8+7
    const int bg    = blockIdx.x >> 5;   // batches bg*16 .. bg*16+15

    unsigned smem_base;
    asm("{ .reg .u64 t; cvta.to.shared.u64 t, %1; cvt.u32.u64 %0, t; }"
        : "=r"(smem_base) : "l"(sm));
    const unsigned mbar = smem_base + OFF_MBAR * 4;

    if (tid == 0) {
        asm volatile("mbarrier.init.shared.b64 [%0], %1;" :: "r"(mbar), "r"(1u) : "memory");
    }

    // ---- Load weights into SMEM ----
    for (int i = tid; i < 32 * FEAT; i += TPB) {
        int r = i / FEAT, k = i - r * FEAT;
        int grow = (r >> 3) * 256 + slice * 8 + (r & 7);
        sm[OFF_W0X + r * XS + k] = g_Wfold[grow * FEAT + k];
    }
    for (int i = tid; i < 32 * HID; i += TPB) {
        int r = i >> 8, k = i & 255;
        int grow = (r >> 3) * 256 + slice * 8 + (r & 7);
        sm[OFF_W0H + r * HS + k] = W_hh0[grow * HID + k];
        sm[OFF_W1A + r * HS + k] = W_ih1[grow * HID + k];
        sm[OFF_W1B + r * HS + k] = W_hh1[grow * HID + k];
    }

    // ---- Per-thread role: one (layer, batch, unit) cell ----
    const int layer = wid >> 2;                        // warps 0-3: L0, 4-7: L1
    const int u     = lane & 7;
    const int bl    = (wid & 3) * 4 + (lane >> 3);     // 0..15
    const int bglob = bg * 16 + bl;

    float bias[4], wout = 0.f;
    {
        const float* bsrc = layer ? g_bias1 : g_bias0;
        #pragma unroll
        for (int g = 0; g < 4; g++) bias[g] = bsrc[g * 256 + slice * 8 + u];
        if (layer) wout = W_out[slice * 8 + u];
    }
    float cst = 0.f;
    __syncthreads();

    // ---- Wavefront: step s computes h0[s] (layer0) and h1[s-1] (layer1) ----
    for (int s = 0; s <= S_LEN; s++) {

        // 1. warp0 polls the 32 producer flags of this batch group (32 lanes)
        if (wid == 0) {
            if (s > 0) {
                const unsigned* fp = &g_flags[bg * NSL + lane];
                unsigned v;
                do {
                    asm volatile("ld.acquire.gpu.global.u32 %0, [%1];"
                                 : "=r"(v) : "l"(fp) : "memory");
                } while (__any_sync(0xffffffffu, v < (unsigned)s));
                __syncwarp();
            }
            // 2. tid0 issues ONE h bulk copy + ONE x bulk copy
            if (lane == 0) {
                asm volatile("mbarrier.arrive.expect_tx.shared.b64 _, [%0], %1;"
                             :: "r"(mbar), "r"(TX_BYTES) : "memory");
                bulk_g2s(smem_base + OFF_H0B * 4,
                         &g_hbuf[(s + 1) & 1][bg][0][0][0], H_COPY_BYTES, mbar);
                bulk_g2s(smem_base + OFF_XB * 4,
                         &g_xT[s][bg][0][0], X_COPY_BYTES, mbar);
            }
        }

        // 3. all threads sleep on the mbarrier (phase parity = s&1)
        mbar_wait(mbar, (unsigned)(s & 1));

        // 4. GEMM (full-K, packed f32x2) + activation + publish
        if (layer == 0) {
            if (s < S_LEN) {
                unsigned long long p0 = pack2(bias[0], 0.f), p1 = pack2(bias[1], 0.f);
                unsigned long long p2 = pack2(bias[2], 0.f), p3 = pack2(bias[3], 0.f);
                gpart2<10, XS>(sm + OFF_W0X + u * XS, sm + OFF_XB + bl * XS, p0, p1, p2, p3);
                gpart2<64, HS>(sm + OFF_W0H + u * HS, sm + OFF_H0B + bl * HS, p0, p1, p2, p3);
                float iv = sig_(hsum2(p0)), fv = sig_(hsum2(p1));
                float gv = tanh_(hsum2(p2)), ov = sig_(hsum2(p3));
                cst = fv * cst + iv * gv;
                float h = ov * tanh_(cst);
                __stcg(&g_hbuf[s & 1][bg][0][bl][slice * 8 + u], h);
            }
        } else {
            if (s >= 1) {
                unsigned long long p0 = pack2(bias[0], 0.f), p1 = pack2(bias[1], 0.f);
                unsigned long long p2 = pack2(bias[2], 0.f), p3 = pack2(bias[3], 0.f);
                gpart2<64, HS>(sm + OFF_W1A + u * HS, sm + OFF_H0B + bl * HS, p0, p1, p2, p3);
                gpart2<64, HS>(sm + OFF_W1B + u * HS, sm + OFF_H1B + bl * HS, p0, p1, p2, p3);
                float iv = sig_(hsum2(p0)), fv = sig_(hsum2(p1));
                float gv = tanh_(hsum2(p2)), ov = sig_(hsum2(p3));
                cst = fv * cst + iv * gv;
                float h = ov * tanh_(cst);
                int tt = s - 1;
                // h1[tt] stored at parity (tt+1)&1 == s&1 (matches h0's parity)
                __stcg(&g_hbuf[s & 1][bg][1][bl][slice * 8 + u], h);
                float pd = h * wout;
                pd += __shfl_down_sync(0xffffffffu, pd, 4, 8);
                pd += __shfl_down_sync(0xffffffffu, pd, 2, 8);
                pd += __shfl_down_sync(0xffffffffu, pd, 1, 8);
                if (u == 0)
                    __stcg(&g_pdot[((size_t)tt * BATCH + bglob) * NSL + slice], pd);
            }
        }

        if (s == S_LEN) break;

        // 5. order stores block-wide, then release this block's flag (plain store)
        __syncthreads();
        if (tid == 0) {
            asm volatile("st.release.gpu.global.u32 [%0], %1;"
                         :: "l"(&g_flags[bg * NSL + slice]), "r"((unsigned)(s + 1))
                         : "memory");
        }
    }
}

// ---------------- Epilogue: reduce partial dots -> output [B,S] ----------------
__global__ void out_kernel(const float* __restrict__ b_out, float* __restrict__ out)
{
    int idx = blockIdx.x * blockDim.x + threadIdx.x;  // idx = b*2048 + t
    int b = idx >> 11, t = idx & 2047;
    const float* p = g_pdot + ((size_t)t * BATCH + b) * NSL;
    float s = b_out[0];
    #pragma unroll
    for (int j = 0; j < NSL; j++) s += p[j];
    out[idx] = s;
}

// ---------------- Launch ----------------
extern "C" void kernel_launch(void* const* d_in, const int* in_sizes, int n_in,
                              void* d_out, int out_size)
{
    const float* in_states = (const float*)d_in[0];
    const float* W_in  = (const float*)d_in[1];
    const float* b_in  = (const float*)d_in[2];
    const float* W_ih0 = (const float*)d_in[3];
    const float* W_hh0 = (const float*)d_in[4];
    const float* b_ih0 = (const float*)d_in[5];
    const float* b_hh0 = (const float*)d_in[6];
    const float* W_ih1 = (const float*)d_in[7];
    const float* W_hh1 = (const float*)d_in[8];
    const float* b_ih1 = (const float*)d_in[9];
    const float* b_hh1 = (const float*)d_in[10];
    const float* W_out = (const float*)d_in[11];
    const float* b_out = (const float*)d_in[12];
    float* out = (float*)d_out;

    cudaFuncSetAttribute(lstm_persist,
                         cudaFuncAttributeMaxDynamicSharedMemorySize, SMEM_BYTES);

    fold_kernel<<<1024, 64>>>(W_ih0, W_in, b_in, b_ih0, b_hh0, b_ih1, b_hh1);
    init_kernel<<<128, 256>>>();
    xT_kernel<<<(BATCH * S_LEN * FEAT + 1023) / 1024, 1024>>>(in_states);
    lstm_persist<<<NBLK, TPB, SMEM_BYTES>>>(W_hh0, W_ih1, W_hh1, W_out);
    out_kernel<<<512, 256>>>(b_out, out);
}